// round 6
// baseline (speedup 1.0000x reference)
#include <cuda_runtime.h>
#include <cstdint>

// Max-unpool 2x2 (kernel=stride=2, non-overlapping).
// x:     [N, C, H, W]   fp32
// where: [N, C, H, W]   int32 in {0..3}
// out:   [N, C, 2H, 2W] fp32
//
// R6: persistent single-wave kernel (148 SMs x 8 CTAs x 256 thr), grid-stride
// over 4-pixel units. Loads 2x LDG.128 (__ldcg), stores 2x STG.256 — all
// streams fully dense. Removes wave-transition DRAM pipeline drains of the
// 8192-CTA one-shot launch.

static constexpr int N = 32, C = 64, H = 64, W = 64;
static constexpr int W4 = W / 4;          // 4-pixel units per input row = 16
static constexpr int OW = 2 * W;          // output width = 128
static constexpr int ROWS = N * C * H;
static constexpr int TOTAL = ROWS * W4;   // 2,097,152 units

static constexpr int NBLOCKS  = 148 * 8;  // one full wave
static constexpr int NTHREADS = 256;

__device__ __forceinline__ void stg256(float* p,
                                       float a, float b, float c, float d,
                                       float e, float f, float g, float h)
{
    asm volatile(
        "st.global.v8.f32 [%0], {%1, %2, %3, %4, %5, %6, %7, %8};"
        :: "l"(p), "f"(a), "f"(b), "f"(c), "f"(d),
           "f"(e), "f"(f), "f"(g), "f"(h)
        : "memory");
}

__device__ __forceinline__ void do_unit(int idx,
                                        const float4* __restrict__ x4,
                                        const int4* __restrict__ w4,
                                        float* __restrict__ out)
{
    int qw  = idx & (W4 - 1);      // unit within row
    int row = idx >> 4;            // (n,c,h)
    int h   = row & (H - 1);
    int nc  = row >> 6;

    float4 xv = __ldcg(&x4[idx]);
    int4   wv = __ldcg(&w4[idx]);

    float t0 = (wv.x == 0) ? xv.x : 0.f;
    float t1 = (wv.x == 1) ? xv.x : 0.f;
    float t2 = (wv.y == 0) ? xv.y : 0.f;
    float t3 = (wv.y == 1) ? xv.y : 0.f;
    float t4 = (wv.z == 0) ? xv.z : 0.f;
    float t5 = (wv.z == 1) ? xv.z : 0.f;
    float t6 = (wv.w == 0) ? xv.w : 0.f;
    float t7 = (wv.w == 1) ? xv.w : 0.f;

    float b0 = (wv.x == 2) ? xv.x : 0.f;
    float b1 = (wv.x == 3) ? xv.x : 0.f;
    float b2 = (wv.y == 2) ? xv.y : 0.f;
    float b3 = (wv.y == 3) ? xv.y : 0.f;
    float b4 = (wv.z == 2) ? xv.z : 0.f;
    float b5 = (wv.z == 3) ? xv.z : 0.f;
    float b6 = (wv.w == 2) ? xv.w : 0.f;
    float b7 = (wv.w == 3) ? xv.w : 0.f;

    size_t obase = (size_t)nc * (2 * H * OW) + (size_t)(2 * h) * OW + (size_t)qw * 8;
    stg256(out + obase,      t0, t1, t2, t3, t4, t5, t6, t7);
    stg256(out + obase + OW, b0, b1, b2, b3, b4, b5, b6, b7);
}

__global__ __launch_bounds__(NTHREADS)
void unpool2x2_kernel(const float4* __restrict__ x4,
                      const int4* __restrict__ w4,
                      float* __restrict__ out)
{
    int stride = NBLOCKS * NTHREADS;                      // 303,104
    for (int idx = blockIdx.x * NTHREADS + threadIdx.x;
         idx < TOTAL; idx += stride) {
        do_unit(idx, x4, w4, out);
    }
}

extern "C" void kernel_launch(void* const* d_in, const int* in_sizes, int n_in,
                              void* d_out, int out_size)
{
    const float4* x4 = (const float4*)d_in[0];
    const int4*   w4 = (const int4*)d_in[1];
    float* out = (float*)d_out;

    unpool2x2_kernel<<<NBLOCKS, NTHREADS>>>(x4, w4, out);
}

// round 7
// speedup vs baseline: 1.1062x; 1.1062x over previous
#include <cuda_runtime.h>
#include <cstdint>

// Max-unpool 2x2 (kernel=stride=2, non-overlapping).
// x:     [N, C, H, W]   fp32
// where: [N, C, H, W]   int32 in {0..3}
// out:   [N, C, 2H, 2W] fp32
//
// R7: lane-pair scheme. Lanes L and L+16 both process unit u = warpbase+(L&15)
// (4 input pixels). Duplicate lane addresses within one LDG are coalesced, so
// read traffic is unchanged. half = L>>4 selects output row 2h (+0) or 2h+1:
// each lane emits ONE STG.256 (32B), and the warp's single store instruction
// covers a fully CONTIGUOUS 1KB block (rows 2h and 2h+1 of one input row).
// Consecutive warps write consecutive 1KB blocks -> perfectly sequential
// write stream per instruction.

static constexpr int N = 32, C = 64, H = 64, W = 64;
static constexpr int W4 = W / 4;          // 4-pixel units per input row = 16
static constexpr int OW = 2 * W;          // output width = 128
static constexpr int ROWS = N * C * H;
static constexpr int TOTAL = ROWS * W4;   // 2,097,152 units
static constexpr int NTHREADS = 256;      // 8 warps, 128 units per block
static constexpr int UNITS_PER_BLOCK = NTHREADS / 2;

__device__ __forceinline__ void stg256(float* p,
                                       float a, float b, float c, float d,
                                       float e, float f, float g, float h)
{
    asm volatile(
        "st.global.v8.f32 [%0], {%1, %2, %3, %4, %5, %6, %7, %8};"
        :: "l"(p), "f"(a), "f"(b), "f"(c), "f"(d),
           "f"(e), "f"(f), "f"(g), "f"(h)
        : "memory");
}

__global__ __launch_bounds__(NTHREADS)
void unpool2x2_kernel(const float4* __restrict__ x4,
                      const int4* __restrict__ w4,
                      float* __restrict__ out)
{
    int lane   = threadIdx.x & 31;
    int warp   = threadIdx.x >> 5;
    int half   = lane >> 4;                 // 0 -> top row, 1 -> bottom row
    int u = (blockIdx.x * UNITS_PER_BLOCK) + warp * 16 + (lane & 15);
    // TOTAL is a multiple of UNITS_PER_BLOCK; grid sized exactly, no guard.

    int qw  = u & (W4 - 1);
    int row = u >> 4;                       // (n,c,h)
    int h   = row & (H - 1);
    int nc  = row >> 6;

    float4 xv = x4[u];                      // lanes L and L+16 dedup-coalesce
    int4   wv = w4[u];

    // Select which window position this half owns: half 0 -> {0,1}, half 1 -> {2,3}
    int s0 = 2 * half;      // 0 or 2
    int s1 = s0 + 1;        // 1 or 3

    float o0 = (wv.x == s0) ? xv.x : 0.f;
    float o1 = (wv.x == s1) ? xv.x : 0.f;
    float o2 = (wv.y == s0) ? xv.y : 0.f;
    float o3 = (wv.y == s1) ? xv.y : 0.f;
    float o4 = (wv.z == s0) ? xv.z : 0.f;
    float o5 = (wv.z == s1) ? xv.z : 0.f;
    float o6 = (wv.w == s0) ? xv.w : 0.f;
    float o7 = (wv.w == s1) ? xv.w : 0.f;

    size_t obase = (size_t)nc * (2 * H * OW)
                 + (size_t)(2 * h + half) * OW
                 + (size_t)qw * 8;
    stg256(out + obase, o0, o1, o2, o3, o4, o5, o6, o7);
}

extern "C" void kernel_launch(void* const* d_in, const int* in_sizes, int n_in,
                              void* d_out, int out_size)
{
    const float4* x4 = (const float4*)d_in[0];
    const int4*   w4 = (const int4*)d_in[1];
    float* out = (float*)d_out;

    int blocks = TOTAL / UNITS_PER_BLOCK;   // 16384
    unpool2x2_kernel<<<blocks, NTHREADS>>>(x4, w4, out);
}

// round 8
// speedup vs baseline: 1.1233x; 1.0154x over previous
#include <cuda_runtime.h>
#include <cstdint>

// Max-unpool 2x2 (kernel=stride=2, non-overlapping).
// x:     [N, C, H, W]   fp32
// where: [N, C, H, W]   int32 in {0..3}
// out:   [N, C, 2H, 2W] fp32
//
// FINAL (R4 config): one thread = 2 input pixels -> one float4 per output
// row. Both read streams and the write stream are fully dense and fully
// sequential; every STG.128 is a full-sector 512B warp transaction.
// Streaming cache policy (__ldcg / __stcs) since nothing is re-touched.
//
// Measured floor: 201 MB compulsory traffic / ~28.45us = ~7.07 TB/s
// aggregate (~88% of 8 TB/s HBM3e spec) — mixed read/write turnaround
// limit. R2/R4/R5/R7 layout variants all land within +-0.5% of this.

static constexpr int N = 32, C = 64, H = 64, W = 64;
static constexpr int W2 = W / 2;          // 2-pixel units per input row = 32
static constexpr int OW = 2 * W;          // output width = 128
static constexpr int ROWS = N * C * H;
static constexpr int TOTAL = ROWS * W2;   // 4,194,304 threads

__global__ __launch_bounds__(256)
void unpool2x2_kernel(const float2* __restrict__ x2,
                      const int2* __restrict__ w2,
                      float* __restrict__ out)
{
    int idx = blockIdx.x * blockDim.x + threadIdx.x;
    if (idx >= TOTAL) return;

    int qw  = idx & (W2 - 1);      // unit within row
    int row = idx >> 5;            // (n,c,h)
    int h   = row & (H - 1);
    int nc  = row >> 6;

    float2 xv = __ldcg(&x2[idx]);
    int2   wv = __ldcg(&w2[idx]);

    // pixel 0 -> cols 0,1 of the 4-span; pixel 1 -> cols 2,3
    float4 top, bot;
    top.x = (wv.x == 0) ? xv.x : 0.f;
    top.y = (wv.x == 1) ? xv.x : 0.f;
    top.z = (wv.y == 0) ? xv.y : 0.f;
    top.w = (wv.y == 1) ? xv.y : 0.f;

    bot.x = (wv.x == 2) ? xv.x : 0.f;
    bot.y = (wv.x == 3) ? xv.x : 0.f;
    bot.z = (wv.y == 2) ? xv.y : 0.f;
    bot.w = (wv.y == 3) ? xv.y : 0.f;

    // 32-bit output offsets (out has 33.5M elements; fits easily)
    unsigned obase = (unsigned)nc * (2 * H * OW)
                   + (unsigned)(2 * h) * OW
                   + (unsigned)qw * 4;
    __stcs(reinterpret_cast<float4*>(out + obase),      top);
    __stcs(reinterpret_cast<float4*>(out + obase + OW), bot);
}

extern "C" void kernel_launch(void* const* d_in, const int* in_sizes, int n_in,
                              void* d_out, int out_size)
{
    const float2* x2 = (const float2*)d_in[0];
    const int2*   w2 = (const int2*)d_in[1];
    float* out = (float*)d_out;

    int threads = 256;
    int blocks = (TOTAL + threads - 1) / threads;   // 16384
    unpool2x2_kernel<<<blocks, threads>>>(x2, w2, out);
}